// round 4
// baseline (speedup 1.0000x reference)
#include <cuda_runtime.h>
#include <math.h>
#include <stdint.h>

#define T_TOK 8192
#define D_DIM 1024
#define F_DIM 4096
#define E_NUM 8
#define A_TOT (2 * T_TOK)  /* 16384 (token, expert) assignments */

// ---------------- scratch (no allocation allowed -> device globals) --------
__device__ int   g_counts[E_NUM];
__device__ int   g_offsets[E_NUM + 1];
__device__ int   g_expidx[A_TOT];
__device__ int   g_pos[A_TOT];
__device__ float g_wt[A_TOT];
__device__ int   g_slot[A_TOT];
__device__ int   g_sorted_tok[A_TOT];
__device__ float g_sorted_wt[A_TOT];
__device__ float g_h[(size_t)A_TOT * F_DIM];              // 256 MB hidden acts (tf32-rounded)
__device__ float g_y[(size_t)A_TOT * D_DIM];              // 64 MB per-assignment outputs
__device__ float g_w1t[(size_t)E_NUM * F_DIM * D_DIM];    // 128 MB: w1^T [e][n(F)][k(D)], tf32
__device__ float g_w2t[(size_t)E_NUM * D_DIM * F_DIM];    // 128 MB: w2^T [e][n(D)][k(F)], tf32

__device__ __forceinline__ float to_tf32(float v) {
    float r;
    asm("cvt.rna.tf32.f32 %0, %1;" : "=f"(r) : "f"(v));
    return r;
}

__device__ __forceinline__ float gelu_exact(float v) {
    return 0.5f * v * (1.0f + erff(v * 0.70710678118654752440f));
}

// m16n8k8 tf32 mma: C[16x8] += A[16x8] * B[8x8]
__device__ __forceinline__ void mma_tf32(float* c, const uint32_t* a,
                                         uint32_t b0, uint32_t b1) {
    asm volatile(
        "mma.sync.aligned.m16n8k8.row.col.f32.tf32.tf32.f32 "
        "{%0,%1,%2,%3}, {%4,%5,%6,%7}, {%8,%9}, {%0,%1,%2,%3};"
        : "+f"(c[0]), "+f"(c[1]), "+f"(c[2]), "+f"(c[3])
        : "r"(a[0]), "r"(a[1]), "r"(a[2]), "r"(a[3]), "r"(b0), "r"(b1));
}

// ---------------------------------------------------------------------------
__global__ void zero_kernel() {
    if (threadIdx.x < E_NUM) g_counts[threadIdx.x] = 0;
}

__global__ __launch_bounds__(256) void gate_kernel(const float* __restrict__ x,
                                                   const float* __restrict__ gw) {
    __shared__ float red[256][9];
    const int t = blockIdx.x;
    const int tid = threadIdx.x;
    float acc[8] = {0.f, 0.f, 0.f, 0.f, 0.f, 0.f, 0.f, 0.f};
    const float* xr = x + (size_t)t * D_DIM;
    for (int j = tid; j < D_DIM; j += 256) {
        float xv = xr[j];
        const float* g = gw + j * E_NUM;
#pragma unroll
        for (int e = 0; e < 8; e++) acc[e] += xv * g[e];
    }
#pragma unroll
    for (int e = 0; e < 8; e++) red[tid][e] = acc[e];
    __syncthreads();
    for (int s = 128; s > 0; s >>= 1) {
        if (tid < s) {
#pragma unroll
            for (int e = 0; e < 8; e++) red[tid][e] += red[tid + s][e];
        }
        __syncthreads();
    }
    if (tid == 0) {
        float v[8];
#pragma unroll
        for (int e = 0; e < 8; e++) v[e] = red[0][e];
        int i0 = 0;
#pragma unroll
        for (int e = 1; e < 8; e++) if (v[e] > v[i0]) i0 = e;
        int i1 = (i0 == 0) ? 1 : 0;
#pragma unroll
        for (int e = 0; e < 8; e++) if (e != i1 && e != i0 && v[e] > v[i1]) i1 = e;
        float e1 = expf(v[i1] - v[i0]);
        float inv = 1.0f / (1.0f + e1);
        int p0 = atomicAdd(&g_counts[i0], 1);
        int p1 = atomicAdd(&g_counts[i1], 1);
        g_expidx[2 * t + 0] = i0;
        g_expidx[2 * t + 1] = i1;
        g_pos[2 * t + 0] = p0;
        g_pos[2 * t + 1] = p1;
        g_wt[2 * t + 0] = inv;
        g_wt[2 * t + 1] = e1 * inv;
    }
}

__global__ void scan_kernel() {
    if (threadIdx.x == 0) {
        int s = 0;
#pragma unroll
        for (int e = 0; e < E_NUM; e++) { g_offsets[e] = s; s += g_counts[e]; }
        g_offsets[E_NUM] = s;
    }
}

__global__ void scatter_kernel() {
    int i = blockIdx.x * 256 + threadIdx.x;
    if (i >= A_TOT) return;
    int e = g_expidx[i];
    int s = g_offsets[e] + g_pos[i];
    g_slot[i] = s;
    g_sorted_tok[s] = i >> 1;
    g_sorted_wt[s] = g_wt[i];
}

// Transpose per-expert [R][C] -> [C][R], rounding to tf32.
__global__ __launch_bounds__(256) void transpose_kernel(const float* __restrict__ src,
                                                        float* __restrict__ dst,
                                                        int R, int C) {
    __shared__ float tile[32][33];
    const int e = blockIdx.z;
    src += (size_t)e * R * C;
    dst += (size_t)e * R * C;
    const int c0 = blockIdx.x * 32;
    const int r0 = blockIdx.y * 32;
    const int tx = threadIdx.x;  // 32
    const int ty = threadIdx.y;  // 8
#pragma unroll
    for (int i = 0; i < 4; i++) {
        int r = r0 + ty + i * 8;
        tile[ty + i * 8][tx] = src[(size_t)r * C + c0 + tx];
    }
    __syncthreads();
#pragma unroll
    for (int i = 0; i < 4; i++) {
        int c = c0 + ty + i * 8;
        dst[(size_t)c * R + r0 + tx] = to_tf32(tile[tx][ty + i * 8]);
    }
}

// ---------------- mma.sync tf32 grouped GEMM --------------------------------
// CTA tile 128(M) x 128(N), K chunks of 16. 4 warps as 2(M) x 2(N), warp tile
// 64x64. Fragment-major smem with 16B pad per fragment block:
//   fa[buf][s*8+mb][lane(32)][4] stride 132 floats (528B) per block.
// Staging: threads 0-63 stage A (unit = (mb,g): rows r,r+8 full K16),
// threads 64-127 stage B likewise from K-major wT. Register 2x2 transpose
// then 8 conflict-free STS.128 per thread (replaces 16 4-way-conflicted STS.32).
#define FRAG_STRIDE 132            /* 32 lanes * 4 + 4 pad floats */
#define BUF_FLOATS (16 * FRAG_STRIDE) /* 2112 floats = 8448 B */

template<int K_TOTAL, int FFN1>
__global__ __launch_bounds__(128, 2)
void ffn_mma(const float* __restrict__ Abase,
             const float* __restrict__ wT,
             const float* __restrict__ bias,
             float* __restrict__ out,
             int out_n) {
    const int e = blockIdx.z;
    const int cnt = g_counts[e];
    const int m0 = blockIdx.y * 128;
    if (m0 >= cnt) return;
    const int off = g_offsets[e];
    const int n0 = blockIdx.x * 128;

    __shared__ __align__(16) float fa[2][BUF_FLOATS];
    __shared__ __align__(16) float fb[2][BUF_FLOATS];
    __shared__ int toks[128];

    const int tid = threadIdx.x;
    const int wid = tid >> 5;
    const int lane = tid & 31;
    const int warp_m = wid >> 1;   // 0..1
    const int warp_n = wid & 1;    // 0..1

    if (tid < 128) {
        int m = m0 + tid;
        if (m >= cnt) m = cnt - 1;
        toks[tid] = FFN1 ? g_sorted_tok[off + m] : (off + m);
    }
    __syncthreads();

    // ---- staging assignment (every thread stages exactly one unit) ----
    const bool isA = (tid < 64);
    const int blk = (isA ? tid : tid - 64) >> 3;  // mb (A) or pair (B), 0..7
    const int sg = (isA ? tid : tid - 64) & 7;    // g, 0..7
    const float* src0;
    const float* src1;
    if (isA) {
        src0 = Abase + (size_t)toks[blk * 16 + sg] * K_TOTAL;
        src1 = Abase + (size_t)toks[blk * 16 + sg + 8] * K_TOTAL;
    } else {
        const float* Bsrc = wT + ((size_t)e * out_n + n0) * K_TOTAL;
        src0 = Bsrc + (size_t)(blk * 16 + sg) * K_TOTAL;
        src1 = Bsrc + (size_t)(blk * 16 + sg + 8) * K_TOTAL;
    }
    float* myfrag = isA ? &fa[0][0] : &fb[0][0];

    float c[4][8][4];
#pragma unroll
    for (int mi = 0; mi < 4; mi++)
#pragma unroll
        for (int ni = 0; ni < 8; ni++)
#pragma unroll
            for (int j = 0; j < 4; j++) c[mi][ni][j] = 0.0f;

    constexpr int NCHUNK = K_TOTAL / 16;
    float rr[2][16];  // [row][kq*4+j] : 2 rows x K16

    // helper lambdas via macros: stage rr -> buffer bufsel
#define STAGE_TO(bufsel) do {                                                  \
    float* base = myfrag + (bufsel) * BUF_FLOATS;                              \
    _Pragma("unroll")                                                          \
    for (int s = 0; s < 2; s++) {                                              \
        _Pragma("unroll")                                                      \
        for (int t = 0; t < 4; t++) {                                          \
            float4 val;                                                        \
            if (isA) {                                                         \
                val.x = rr[0][(2 * s) * 4 + t];                                \
                val.y = rr[1][(2 * s) * 4 + t];                                \
                val.z = rr[0][(2 * s + 1) * 4 + t];                            \
                val.w = rr[1][(2 * s + 1) * 4 + t];                            \
            } else {                                                           \
                val.x = rr[0][(2 * s) * 4 + t];                                \
                val.y = rr[0][(2 * s + 1) * 4 + t];                            \
                val.z = rr[1][(2 * s) * 4 + t];                                \
                val.w = rr[1][(2 * s + 1) * 4 + t];                            \
            }                                                                  \
            if (FFN1 && isA) {                                                 \
                val.x = to_tf32(val.x); val.y = to_tf32(val.y);                \
                val.z = to_tf32(val.z); val.w = to_tf32(val.w);                \
            }                                                                  \
            *(float4*)&base[(s * 8 + blk) * FRAG_STRIDE + (sg * 4 + t) * 4] = val; \
        }                                                                      \
    }                                                                          \
} while (0)

#define LOAD_CHUNK(k0) do {                                                    \
    _Pragma("unroll")                                                          \
    for (int kq = 0; kq < 4; kq++) {                                           \
        *(float4*)&rr[0][kq * 4] = *(const float4*)(src0 + (k0) + kq * 4);     \
        *(float4*)&rr[1][kq * 4] = *(const float4*)(src1 + (k0) + kq * 4);     \
    }                                                                          \
} while (0)

    // Prologue: chunk 0.
    LOAD_CHUNK(0);
    STAGE_TO(0);
    __syncthreads();

    for (int ch = 0; ch < NCHUNK; ch++) {
        const int b = ch & 1;
        const bool more = (ch + 1 < NCHUNK);
        if (more) LOAD_CHUNK((ch + 1) * 16);

        // Compute from buffer b.
#pragma unroll
        for (int s = 0; s < 2; s++) {
            uint4 afr[4];
#pragma unroll
            for (int mi = 0; mi < 4; mi++) {
                int mb = warp_m * 4 + mi;
                afr[mi] = *(const uint4*)&fa[b][(s * 8 + mb) * FRAG_STRIDE + lane * 4];
            }
#pragma unroll
            for (int pi = 0; pi < 4; pi++) {
                int pb = warp_n * 4 + pi;
                uint4 bf = *(const uint4*)&fb[b][(s * 8 + pb) * FRAG_STRIDE + lane * 4];
#pragma unroll
                for (int mi = 0; mi < 4; mi++) {
                    mma_tf32(c[mi][2 * pi + 0], (const uint32_t*)&afr[mi], bf.x, bf.y);
                    mma_tf32(c[mi][2 * pi + 1], (const uint32_t*)&afr[mi], bf.z, bf.w);
                }
            }
        }
        if (more) STAGE_TO(b ^ 1);
        __syncthreads();
    }
#undef STAGE_TO
#undef LOAD_CHUNK

    // Epilogue. c[mi][ni][q]: rows warp_m*64 + mi*16 + g (+8 for q>=2),
    // cols warp_n*64 + ni*8 + t*2 (+1).
    const int g = lane >> 2;
    const int t = lane & 3;
    const float* brow = bias + (size_t)e * out_n + n0;
#pragma unroll
    for (int mi = 0; mi < 4; mi++) {
#pragma unroll
        for (int half = 0; half < 2; half++) {
            int r = warp_m * 64 + mi * 16 + g + half * 8;
            int mglob = m0 + r;
            if (mglob >= cnt) continue;
            size_t srow = (size_t)(off + mglob);
            float wt = 1.0f;
            if (!FFN1) wt = g_sorted_wt[srow];
            float* orow = out + srow * (size_t)out_n + n0;
#pragma unroll
            for (int ni = 0; ni < 8; ni++) {
                int col = warp_n * 64 + ni * 8 + t * 2;
                float2 bb = *(const float2*)(brow + col);
                float v0 = c[mi][ni][half * 2 + 0] + bb.x;
                float v1 = c[mi][ni][half * 2 + 1] + bb.y;
                float2 o;
                if (FFN1) {
                    o.x = to_tf32(gelu_exact(v0));
                    o.y = to_tf32(gelu_exact(v1));
                } else {
                    o.x = wt * v0;
                    o.y = wt * v1;
                }
                *(float2*)(orow + col) = o;
            }
        }
    }
}

// out[t, d] = y[slot0(t), d] + y[slot1(t), d]
__global__ __launch_bounds__(256) void combine_kernel(float* __restrict__ out) {
    int i = blockIdx.x * 256 + threadIdx.x;
    int t = i >> 10;
    int d = i & 1023;
    int s0 = g_slot[2 * t + 0];
    int s1 = g_slot[2 * t + 1];
    out[i] = g_y[(size_t)s0 * D_DIM + d] + g_y[(size_t)s1 * D_DIM + d];
}

// ---------------------------------------------------------------------------
extern "C" void kernel_launch(void* const* d_in, const int* in_sizes, int n_in,
                              void* d_out, int out_size) {
    const float* x  = (const float*)d_in[0];
    const float* gw = (const float*)d_in[1];
    const float* w1 = (const float*)d_in[2];
    const float* b1 = (const float*)d_in[3];
    const float* w2 = (const float*)d_in[4];
    const float* b2 = (const float*)d_in[5];
    float* out = (float*)d_out;

    float* w1t; cudaGetSymbolAddress((void**)&w1t, g_w1t);
    float* w2t; cudaGetSymbolAddress((void**)&w2t, g_w2t);
    float* hbuf; cudaGetSymbolAddress((void**)&hbuf, g_h);
    float* ybuf; cudaGetSymbolAddress((void**)&ybuf, g_y);

    zero_kernel<<<1, 32>>>();
    gate_kernel<<<T_TOK, 256>>>(x, gw);
    scan_kernel<<<1, 32>>>();
    scatter_kernel<<<A_TOT / 256, 256>>>();

    // w1 [e][D][F] -> w1t [e][F][D]; w2 [e][F][D] -> w2t [e][D][F]  (tf32-rounded)
    transpose_kernel<<<dim3(F_DIM / 32, D_DIM / 32, E_NUM), dim3(32, 8)>>>(w1, w1t, D_DIM, F_DIM);
    transpose_kernel<<<dim3(D_DIM / 32, F_DIM / 32, E_NUM), dim3(32, 8)>>>(w2, w2t, F_DIM, D_DIM);

    // GEMM1: h = gelu(x @ w1 + b1); oversized grid (y covers worst-case expert
    // imbalance A_TOT/128 = 128), blocks early-exit on counts.
    ffn_mma<D_DIM, 1><<<dim3(F_DIM / 128, A_TOT / 128, E_NUM), 128>>>(
        x, w1t, b1, hbuf, F_DIM);
    // GEMM2: y = wt * (h @ w2 + b2)
    ffn_mma<F_DIM, 0><<<dim3(D_DIM / 128, A_TOT / 128, E_NUM), 128>>>(
        hbuf, w2t, b2, ybuf, D_DIM);

    combine_kernel<<<(T_TOK * D_DIM) / 256, 256>>>(out);
}

// round 5
// speedup vs baseline: 1.4916x; 1.4916x over previous
#include <cuda_runtime.h>
#include <math.h>
#include <stdint.h>

#define T_TOK 8192
#define D_DIM 1024
#define F_DIM 4096
#define E_NUM 8
#define A_TOT (2 * T_TOK)  /* 16384 (token, expert) assignments */

// ---------------- scratch (no allocation allowed -> device globals) --------
__device__ int   g_counts[E_NUM];
__device__ int   g_offsets[E_NUM + 1];
__device__ int   g_expidx[A_TOT];
__device__ int   g_pos[A_TOT];
__device__ float g_wt[A_TOT];
__device__ int   g_slot[A_TOT];
__device__ int   g_sorted_tok[A_TOT];
__device__ float g_sorted_wt[A_TOT];
__device__ float g_h[(size_t)A_TOT * F_DIM];              // 256 MB hidden acts (tf32-rounded)
__device__ float g_y[(size_t)A_TOT * D_DIM];              // 64 MB per-assignment outputs
__device__ float g_w1t[(size_t)E_NUM * F_DIM * D_DIM];    // 128 MB: w1^T [e][n(F)][k(D)], tf32
__device__ float g_w2t[(size_t)E_NUM * D_DIM * F_DIM];    // 128 MB: w2^T [e][n(D)][k(F)], tf32

__device__ __forceinline__ float to_tf32(float v) {
    float r;
    asm("cvt.rna.tf32.f32 %0, %1;" : "=f"(r) : "f"(v));
    return r;
}

__device__ __forceinline__ float gelu_exact(float v) {
    return 0.5f * v * (1.0f + erff(v * 0.70710678118654752440f));
}

// m16n8k8 tf32 mma: C[16x8] += A[16x8] * B[8x8]
__device__ __forceinline__ void mma_tf32(float* c, const uint32_t* a,
                                         uint32_t b0, uint32_t b1) {
    asm volatile(
        "mma.sync.aligned.m16n8k8.row.col.f32.tf32.tf32.f32 "
        "{%0,%1,%2,%3}, {%4,%5,%6,%7}, {%8,%9}, {%0,%1,%2,%3};"
        : "+f"(c[0]), "+f"(c[1]), "+f"(c[2]), "+f"(c[3])
        : "r"(a[0]), "r"(a[1]), "r"(a[2]), "r"(a[3]), "r"(b0), "r"(b1));
}

// ---------------------------------------------------------------------------
__global__ void zero_kernel() {
    if (threadIdx.x < E_NUM) g_counts[threadIdx.x] = 0;
}

__global__ __launch_bounds__(256) void gate_kernel(const float* __restrict__ x,
                                                   const float* __restrict__ gw) {
    __shared__ float red[256][9];
    const int t = blockIdx.x;
    const int tid = threadIdx.x;
    float acc[8] = {0.f, 0.f, 0.f, 0.f, 0.f, 0.f, 0.f, 0.f};
    const float* xr = x + (size_t)t * D_DIM;
    for (int j = tid; j < D_DIM; j += 256) {
        float xv = xr[j];
        const float* g = gw + j * E_NUM;
#pragma unroll
        for (int e = 0; e < 8; e++) acc[e] += xv * g[e];
    }
#pragma unroll
    for (int e = 0; e < 8; e++) red[tid][e] = acc[e];
    __syncthreads();
    for (int s = 128; s > 0; s >>= 1) {
        if (tid < s) {
#pragma unroll
            for (int e = 0; e < 8; e++) red[tid][e] += red[tid + s][e];
        }
        __syncthreads();
    }
    if (tid == 0) {
        float v[8];
#pragma unroll
        for (int e = 0; e < 8; e++) v[e] = red[0][e];
        int i0 = 0;
#pragma unroll
        for (int e = 1; e < 8; e++) if (v[e] > v[i0]) i0 = e;
        int i1 = (i0 == 0) ? 1 : 0;
#pragma unroll
        for (int e = 0; e < 8; e++) if (e != i1 && e != i0 && v[e] > v[i1]) i1 = e;
        float e1 = expf(v[i1] - v[i0]);
        float inv = 1.0f / (1.0f + e1);
        int p0 = atomicAdd(&g_counts[i0], 1);
        int p1 = atomicAdd(&g_counts[i1], 1);
        g_expidx[2 * t + 0] = i0;
        g_expidx[2 * t + 1] = i1;
        g_pos[2 * t + 0] = p0;
        g_pos[2 * t + 1] = p1;
        g_wt[2 * t + 0] = inv;
        g_wt[2 * t + 1] = e1 * inv;
    }
}

__global__ void scan_kernel() {
    if (threadIdx.x == 0) {
        int s = 0;
#pragma unroll
        for (int e = 0; e < E_NUM; e++) { g_offsets[e] = s; s += g_counts[e]; }
        g_offsets[E_NUM] = s;
    }
}

__global__ void scatter_kernel() {
    int i = blockIdx.x * 256 + threadIdx.x;
    if (i >= A_TOT) return;
    int e = g_expidx[i];
    int s = g_offsets[e] + g_pos[i];
    g_slot[i] = s;
    g_sorted_tok[s] = i >> 1;
    g_sorted_wt[s] = g_wt[i];
}

// Transpose per-expert [R][C] -> [C][R], rounding to tf32.
__global__ __launch_bounds__(256) void transpose_kernel(const float* __restrict__ src,
                                                        float* __restrict__ dst,
                                                        int R, int C) {
    __shared__ float tile[32][33];
    const int e = blockIdx.z;
    src += (size_t)e * R * C;
    dst += (size_t)e * R * C;
    const int c0 = blockIdx.x * 32;
    const int r0 = blockIdx.y * 32;
    const int tx = threadIdx.x;  // 32
    const int ty = threadIdx.y;  // 8
#pragma unroll
    for (int i = 0; i < 4; i++) {
        int r = r0 + ty + i * 8;
        tile[ty + i * 8][tx] = src[(size_t)r * C + c0 + tx];
    }
    __syncthreads();
#pragma unroll
    for (int i = 0; i < 4; i++) {
        int c = c0 + ty + i * 8;
        dst[(size_t)c * R + r0 + tx] = to_tf32(tile[tx][ty + i * 8]);
    }
}

// ---------------- mma.sync tf32 grouped GEMM --------------------------------
// CTA tile 128(M) x 128(N), K chunks of 16. 8 warps as 4(M) x 2(N), warp tile
// 32x64 (R3 structure: 16 warps/SM for latency hiding).
// Fragment-major smem, block index = (frag*2 + s), FRAG_STRIDE=132 floats
// (528 B: 33x16B, odd in 16B-block units mod 8 -> the four 128B groups a
// warp's STS touches land on distinct bank footprints; LDS.128 lane-contig).
// Staging unit per thread: (2 rows x K8) -> 4 LDG.128 + reg transpose +
// 4 conflict-free STS.128. tids 0-127 stage A, 128-255 stage B.
#define FRAG_STRIDE 132
#define BUF_FLOATS (16 * FRAG_STRIDE) /* 2112 floats = 8448 B */

template<int K_TOTAL, int FFN1>
__global__ __launch_bounds__(256, 2)
void ffn_mma(const float* __restrict__ Abase,
             const float* __restrict__ wT,
             const float* __restrict__ bias,
             float* __restrict__ out,
             int out_n) {
    const int e = blockIdx.z;
    const int cnt = g_counts[e];
    const int m0 = blockIdx.y * 128;
    if (m0 >= cnt) return;
    const int off = g_offsets[e];
    const int n0 = blockIdx.x * 128;

    __shared__ __align__(16) float fa[2][BUF_FLOATS];
    __shared__ __align__(16) float fb[2][BUF_FLOATS];
    __shared__ int toks[128];

    const int tid = threadIdx.x;
    const int wid = tid >> 5;
    const int lane = tid & 31;
    const int warp_m = wid >> 1;   // 0..3
    const int warp_n = wid & 1;    // 0..1

    if (tid < 128) {
        int m = m0 + tid;
        if (m >= cnt) m = cnt - 1;
        toks[tid] = FFN1 ? g_sorted_tok[off + m] : (off + m);
    }
    __syncthreads();

    // ---- staging assignment: one unit per thread ----
    // unit = (blk 0..7, g 0..7, us 0..1): rows r0=blk*16+g, r1=r0+8, k-half us.
    const bool isA = (tid < 128);
    const int uid = isA ? tid : (tid - 128);
    const int blk = uid >> 4;
    const int sg  = (uid >> 1) & 7;
    const int us  = uid & 1;
    const int r0i = blk * 16 + sg;
    const float* src0;
    const float* src1;
    if (isA) {
        src0 = Abase + (size_t)toks[r0i] * K_TOTAL;
        src1 = Abase + (size_t)toks[r0i + 8] * K_TOTAL;
    } else {
        const float* Bsrc = wT + ((size_t)e * out_n + n0) * K_TOTAL;
        src0 = Bsrc + (size_t)r0i * K_TOTAL;
        src1 = Bsrc + (size_t)(r0i + 8) * K_TOTAL;
    }
    // block index (frag*2 + us), lane slot = sg*4 + t
    float* stage_base0 = (isA ? &fa[0][0] : &fb[0][0]) + (blk * 2 + us) * FRAG_STRIDE;

    float c[2][8][4];
#pragma unroll
    for (int mi = 0; mi < 2; mi++)
#pragma unroll
        for (int ni = 0; ni < 8; ni++)
#pragma unroll
            for (int j = 0; j < 4; j++) c[mi][ni][j] = 0.0f;

    constexpr int NCHUNK = K_TOTAL / 16;
    float rr[2][8];  // 2 rows x 8 k (this thread's k-half)

#define LOAD_CHUNK(k0) do {                                                    \
    *(float4*)&rr[0][0] = *(const float4*)(src0 + (k0) + us * 8);              \
    *(float4*)&rr[0][4] = *(const float4*)(src0 + (k0) + us * 8 + 4);          \
    *(float4*)&rr[1][0] = *(const float4*)(src1 + (k0) + us * 8);              \
    *(float4*)&rr[1][4] = *(const float4*)(src1 + (k0) + us * 8 + 4);          \
} while (0)

#define STAGE_TO(bufsel) do {                                                  \
    float* base = stage_base0 + (bufsel) * BUF_FLOATS;                         \
    _Pragma("unroll")                                                          \
    for (int t = 0; t < 4; t++) {                                              \
        float4 val;                                                            \
        if (isA) {                                                             \
            val.x = rr[0][t];     val.y = rr[1][t];                            \
            val.z = rr[0][4 + t]; val.w = rr[1][4 + t];                        \
            if (FFN1) {                                                        \
                val.x = to_tf32(val.x); val.y = to_tf32(val.y);                \
                val.z = to_tf32(val.z); val.w = to_tf32(val.w);                \
            }                                                                  \
        } else {                                                               \
            val.x = rr[0][t];     val.y = rr[0][4 + t];                        \
            val.z = rr[1][t];     val.w = rr[1][4 + t];                        \
        }                                                                      \
        *(float4*)&base[(sg * 4 + t) * 4] = val;                               \
    }                                                                          \
} while (0)

    // Prologue: chunk 0.
    LOAD_CHUNK(0);
    STAGE_TO(0);
    __syncthreads();

    for (int ch = 0; ch < NCHUNK; ch++) {
        const int b = ch & 1;
        const bool more = (ch + 1 < NCHUNK);
        if (more) LOAD_CHUNK((ch + 1) * 16);

        // Compute from buffer b.
#pragma unroll
        for (int s = 0; s < 2; s++) {
            uint4 afr[2];
#pragma unroll
            for (int mi = 0; mi < 2; mi++) {
                int mb = warp_m * 2 + mi;
                afr[mi] = *(const uint4*)&fa[b][(mb * 2 + s) * FRAG_STRIDE + lane * 4];
            }
#pragma unroll
            for (int pi = 0; pi < 4; pi++) {
                int pb = warp_n * 4 + pi;
                uint4 bf = *(const uint4*)&fb[b][(pb * 2 + s) * FRAG_STRIDE + lane * 4];
#pragma unroll
                for (int mi = 0; mi < 2; mi++) {
                    mma_tf32(c[mi][2 * pi + 0], (const uint32_t*)&afr[mi], bf.x, bf.y);
                    mma_tf32(c[mi][2 * pi + 1], (const uint32_t*)&afr[mi], bf.z, bf.w);
                }
            }
        }
        if (more) STAGE_TO(b ^ 1);
        __syncthreads();
    }
#undef STAGE_TO
#undef LOAD_CHUNK

    // Epilogue. c[mi][ni][q]: rows warp_m*32 + mi*16 + g (+8 for q>=2),
    // cols warp_n*64 + ni*8 + t*2 (+1).
    const int g = lane >> 2;
    const int t = lane & 3;
    const float* brow = bias + (size_t)e * out_n + n0;
#pragma unroll
    for (int mi = 0; mi < 2; mi++) {
#pragma unroll
        for (int half = 0; half < 2; half++) {
            int r = warp_m * 32 + mi * 16 + g + half * 8;
            int mglob = m0 + r;
            if (mglob >= cnt) continue;
            size_t srow = (size_t)(off + mglob);
            float wt = 1.0f;
            if (!FFN1) wt = g_sorted_wt[srow];
            float* orow = out + srow * (size_t)out_n + n0;
#pragma unroll
            for (int ni = 0; ni < 8; ni++) {
                int col = warp_n * 64 + ni * 8 + t * 2;
                float2 bb = *(const float2*)(brow + col);
                float v0 = c[mi][ni][half * 2 + 0] + bb.x;
                float v1 = c[mi][ni][half * 2 + 1] + bb.y;
                float2 o;
                if (FFN1) {
                    o.x = to_tf32(gelu_exact(v0));
                    o.y = to_tf32(gelu_exact(v1));
                } else {
                    o.x = wt * v0;
                    o.y = wt * v1;
                }
                *(float2*)(orow + col) = o;
            }
        }
    }
}

// out[t, d] = y[slot0(t), d] + y[slot1(t), d]
__global__ __launch_bounds__(256) void combine_kernel(float* __restrict__ out) {
    int i = blockIdx.x * 256 + threadIdx.x;
    int t = i >> 10;
    int d = i & 1023;
    int s0 = g_slot[2 * t + 0];
    int s1 = g_slot[2 * t + 1];
    out[i] = g_y[(size_t)s0 * D_DIM + d] + g_y[(size_t)s1 * D_DIM + d];
}

// ---------------------------------------------------------------------------
extern "C" void kernel_launch(void* const* d_in, const int* in_sizes, int n_in,
                              void* d_out, int out_size) {
    const float* x  = (const float*)d_in[0];
    const float* gw = (const float*)d_in[1];
    const float* w1 = (const float*)d_in[2];
    const float* b1 = (const float*)d_in[3];
    const float* w2 = (const float*)d_in[4];
    const float* b2 = (const float*)d_in[5];
    float* out = (float*)d_out;

    float* w1t; cudaGetSymbolAddress((void**)&w1t, g_w1t);
    float* w2t; cudaGetSymbolAddress((void**)&w2t, g_w2t);
    float* hbuf; cudaGetSymbolAddress((void**)&hbuf, g_h);
    float* ybuf; cudaGetSymbolAddress((void**)&ybuf, g_y);

    zero_kernel<<<1, 32>>>();
    gate_kernel<<<T_TOK, 256>>>(x, gw);
    scan_kernel<<<1, 32>>>();
    scatter_kernel<<<A_TOT / 256, 256>>>();

    // w1 [e][D][F] -> w1t [e][F][D]; w2 [e][F][D] -> w2t [e][D][F]  (tf32-rounded)
    transpose_kernel<<<dim3(F_DIM / 32, D_DIM / 32, E_NUM), dim3(32, 8)>>>(w1, w1t, D_DIM, F_DIM);
    transpose_kernel<<<dim3(D_DIM / 32, F_DIM / 32, E_NUM), dim3(32, 8)>>>(w2, w2t, F_DIM, D_DIM);

    // GEMM1: h = gelu(x @ w1 + b1); oversized grid (y covers worst-case expert
    // imbalance A_TOT/128 = 128), blocks early-exit on counts.
    ffn_mma<D_DIM, 1><<<dim3(F_DIM / 128, A_TOT / 128, E_NUM), 256>>>(
        x, w1t, b1, hbuf, F_DIM);
    // GEMM2: y = wt * (h @ w2 + b2)
    ffn_mma<F_DIM, 0><<<dim3(D_DIM / 128, A_TOT / 128, E_NUM), 256>>>(
        hbuf, w2t, b2, ybuf, D_DIM);

    combine_kernel<<<(T_TOK * D_DIM) / 256, 256>>>(out);
}

// round 6
// speedup vs baseline: 2.1997x; 1.4747x over previous
#include <cuda_runtime.h>
#include <math.h>
#include <stdint.h>

#define T_TOK 8192
#define D_DIM 1024
#define F_DIM 4096
#define E_NUM 8
#define A_TOT (2 * T_TOK)      /* 16384 real (token, expert) assignments */
#define A_PAD 17408            /* A_TOT + 8*128 padding, multiple of 128 */
#define NMT   (A_PAD / 128)    /* 136 global M-tiles */
#define NCH1  (D_DIM / 16)     /* 64 K-chunks, GEMM1 */
#define NCH2  (F_DIM / 16)     /* 256 K-chunks, GEMM2 */
#define NT1   (F_DIM / 128)    /* 32 N-tiles, GEMM1 */
#define NT2   (D_DIM / 128)    /* 8 N-tiles, GEMM2 */

// ---------------- scratch (no allocation allowed -> device globals) --------
__device__ int   g_counts[E_NUM];
__device__ int   g_offsets[E_NUM + 1];          // PADDED offsets (mult of 128)
__device__ int   g_expidx[A_TOT];
__device__ int   g_pos[A_TOT];
__device__ float g_wt[A_TOT];
__device__ int   g_slot[A_TOT];
__device__ int   g_sorted_tok[A_PAD];
__device__ float g_sorted_wt[A_PAD];
// Fragment-major buffers: slab = 2048 floats (16 blocks x 32 lanes x 4).
__device__ float g_xa[(size_t)NMT * NCH1 * 2048];           //  68 MB A-frags GEMM1
__device__ float g_hf[(size_t)NMT * NCH2 * 2048];           // 285 MB A-frags GEMM2 (tf32 h)
__device__ float g_w1f[(size_t)E_NUM * NT1 * NCH1 * 2048];  // 128 MB B-frags GEMM1
__device__ float g_w2f[(size_t)E_NUM * NT2 * NCH2 * 2048];  // 128 MB B-frags GEMM2
__device__ float g_y[(size_t)A_PAD * D_DIM];                //  71 MB per-assignment outputs

__device__ __forceinline__ float to_tf32(float v) {
    float r;
    asm("cvt.rna.tf32.f32 %0, %1;" : "=f"(r) : "f"(v));
    return r;
}

__device__ __forceinline__ float gelu_exact(float v) {
    return 0.5f * v * (1.0f + erff(v * 0.70710678118654752440f));
}

// m16n8k8 tf32 mma: C[16x8] += A[16x8] * B[8x8]
__device__ __forceinline__ void mma_tf32(float* c, const uint32_t* a,
                                         uint32_t b0, uint32_t b1) {
    asm volatile(
        "mma.sync.aligned.m16n8k8.row.col.f32.tf32.tf32.f32 "
        "{%0,%1,%2,%3}, {%4,%5,%6,%7}, {%8,%9}, {%0,%1,%2,%3};"
        : "+f"(c[0]), "+f"(c[1]), "+f"(c[2]), "+f"(c[3])
        : "r"(a[0]), "r"(a[1]), "r"(a[2]), "r"(a[3]), "r"(b0), "r"(b1));
}

// ---------------------------------------------------------------------------
__global__ void zero_kernel() {
    if (threadIdx.x < E_NUM) g_counts[threadIdx.x] = 0;
}

__global__ __launch_bounds__(256) void gate_kernel(const float* __restrict__ x,
                                                   const float* __restrict__ gw) {
    __shared__ float red[256][9];
    const int t = blockIdx.x;
    const int tid = threadIdx.x;
    float acc[8] = {0.f, 0.f, 0.f, 0.f, 0.f, 0.f, 0.f, 0.f};
    const float* xr = x + (size_t)t * D_DIM;
    for (int j = tid; j < D_DIM; j += 256) {
        float xv = xr[j];
        const float* g = gw + j * E_NUM;
#pragma unroll
        for (int e = 0; e < 8; e++) acc[e] += xv * g[e];
    }
#pragma unroll
    for (int e = 0; e < 8; e++) red[tid][e] = acc[e];
    __syncthreads();
    for (int s = 128; s > 0; s >>= 1) {
        if (tid < s) {
#pragma unroll
            for (int e = 0; e < 8; e++) red[tid][e] += red[tid + s][e];
        }
        __syncthreads();
    }
    if (tid == 0) {
        float v[8];
#pragma unroll
        for (int e = 0; e < 8; e++) v[e] = red[0][e];
        int i0 = 0;
#pragma unroll
        for (int e = 1; e < 8; e++) if (v[e] > v[i0]) i0 = e;
        int i1 = (i0 == 0) ? 1 : 0;
#pragma unroll
        for (int e = 0; e < 8; e++) if (e != i1 && e != i0 && v[e] > v[i1]) i1 = e;
        float e1 = expf(v[i1] - v[i0]);
        float inv = 1.0f / (1.0f + e1);
        int p0 = atomicAdd(&g_counts[i0], 1);
        int p1 = atomicAdd(&g_counts[i1], 1);
        g_expidx[2 * t + 0] = i0;
        g_expidx[2 * t + 1] = i1;
        g_pos[2 * t + 0] = p0;
        g_pos[2 * t + 1] = p1;
        g_wt[2 * t + 0] = inv;
        g_wt[2 * t + 1] = e1 * inv;
    }
}

__global__ void scan_kernel() {
    if (threadIdx.x == 0) {
        int s = 0;
#pragma unroll
        for (int e = 0; e < E_NUM; e++) {
            g_offsets[e] = s;
            s += (g_counts[e] + 127) & ~127;   // pad each expert to 128
        }
        g_offsets[E_NUM] = s;
    }
}

__global__ void scatter_kernel() {
    int i = blockIdx.x * 256 + threadIdx.x;
    if (i >= A_TOT) return;
    int e = g_expidx[i];
    int s = g_offsets[e] + g_pos[i];
    g_slot[i] = s;
    g_sorted_tok[s] = i >> 1;
    g_sorted_wt[s] = g_wt[i];
}

// Fill padding slots with tok=0, wt=0.
__global__ void pad_fill_kernel() {
    int s = blockIdx.x * 256 + threadIdx.x;
    if (s >= A_PAD) return;
    int e = 0;
#pragma unroll
    for (int i = 1; i < E_NUM; i++) if (s >= g_offsets[i]) e = i;
    int local = s - g_offsets[e];
    if (local >= g_counts[e]) {
        g_sorted_tok[s] = 0;
        g_sorted_wt[s] = 0.0f;
    }
}

// ---------------- fragment pre-format kernels -------------------------------
// Fragment slab for one (tile, chunk): 16 blocks x 32 lanes x 4 floats = 2048.
// Block id = frag*2 + k-half(us).
// A-style block content (frag=mb): float j at lane slot (sg*4+t):
//   j=0:(r,k) j=1:(r+8,k) j=2:(r,k+4) j=3:(r+8,k+4), r=mb*16+sg, k=us*8+t.
// B-style block content (frag=pb): j=0:(n,k) j=1:(n,k+4) j=2:(n+8,k) j=3:(n+8,k+4).

// Gather routed x rows into A-fragment slabs (tf32-rounded).
__global__ __launch_bounds__(256) void xfrag_kernel(const float* __restrict__ x) {
    const int ch = blockIdx.x;   // 0..NCH1-1
    const int mt = blockIdx.y;   // 0..NMT-1
    __shared__ float sx[128 * 20];
    __shared__ int toks[128];
    const int tid = threadIdx.x;
    if (tid < 128) toks[tid] = g_sorted_tok[mt * 128 + tid];
    __syncthreads();
#pragma unroll
    for (int p = 0; p < 2; p++) {
        int q = tid + p * 256;           // 0..511 float4s
        int row = q >> 2, kq = q & 3;
        float4 v = *(const float4*)(x + (size_t)toks[row] * D_DIM + ch * 16 + kq * 4);
        v.x = to_tf32(v.x); v.y = to_tf32(v.y); v.z = to_tf32(v.z); v.w = to_tf32(v.w);
        *(float4*)&sx[row * 20 + kq * 4] = v;
    }
    __syncthreads();
    float* dst = g_xa + ((size_t)mt * NCH1 + ch) * 2048;
#pragma unroll
    for (int p = 0; p < 2; p++) {
        int q = tid + p * 256;
        int blkid = q >> 5, slot = q & 31;
        int mb = blkid >> 1, us = blkid & 1;
        int sg = slot >> 2, t = slot & 3;
        int r0 = mb * 16 + sg, k0 = us * 8 + t;
        float4 v;
        v.x = sx[r0 * 20 + k0];
        v.y = sx[(r0 + 8) * 20 + k0];
        v.z = sx[r0 * 20 + k0 + 4];
        v.w = sx[(r0 + 8) * 20 + k0 + 4];
        *(float4*)&dst[q * 4] = v;
    }
}

// Reformat weights [e][K][N] row-major -> B-fragment slabs (tf32-rounded).
__global__ __launch_bounds__(256) void wfrag_kernel(const float* __restrict__ w,
                                                    float* __restrict__ dstbase,
                                                    int Ndim) {
    const int nt = blockIdx.x;   // N-tile
    const int ch = blockIdx.y;   // K-chunk
    const int e = blockIdx.z;
    const int Kdim = gridDim.y * 16;
    __shared__ float s[16 * 132];
    const float* src = w + (size_t)e * Kdim * Ndim + (size_t)(ch * 16) * Ndim + nt * 128;
    const int tid = threadIdx.x;
#pragma unroll
    for (int p = 0; p < 2; p++) {
        int q = tid + p * 256;
        int kk = q >> 5, nn = q & 31;
        float4 v = *(const float4*)(src + (size_t)kk * Ndim + nn * 4);
        v.x = to_tf32(v.x); v.y = to_tf32(v.y); v.z = to_tf32(v.z); v.w = to_tf32(v.w);
        *(float4*)&s[kk * 132 + nn * 4] = v;
    }
    __syncthreads();
    float* dst = dstbase + (((size_t)e * gridDim.x + nt) * gridDim.y + ch) * 2048;
#pragma unroll
    for (int p = 0; p < 2; p++) {
        int q = tid + p * 256;
        int blkid = q >> 5, slot = q & 31;
        int pb = blkid >> 1, us = blkid & 1;
        int sg = slot >> 2, t = slot & 3;
        int n0 = pb * 16 + sg, k0 = us * 8 + t;
        float4 v;
        v.x = s[k0 * 132 + n0];
        v.y = s[(k0 + 4) * 132 + n0];
        v.z = s[k0 * 132 + n0 + 8];
        v.w = s[(k0 + 4) * 132 + n0 + 8];
        *(float4*)&dst[q * 4] = v;
    }
}

// ---------------- mma.sync tf32 grouped GEMM --------------------------------
// CTA 128x128, 8 warps 4(M)x2(N), warp tile 32x64 (R5 shape, 16 warps/SM).
// Staging = contiguous 8KB slab copy per chunk (4 LDG.128 + 4 STS.128 per
// thread, lane-linear, conflict-free). Compute identical to R5 (stride 128).
// FFN1: epilogue writes gelu(acc+b1) (tf32) directly into GEMM2 A-fragment
//       layout in g_hf (scattered STG.32, once per CTA).
// FFN2: epilogue writes wt*(acc+b2) row-major to g_y.
template<int NCHUNK, int FFN1>
__global__ __launch_bounds__(256, 2)
void ffn_mma(const float* __restrict__ Afrag,
             const float* __restrict__ Bfrag,
             const float* __restrict__ bias,
             float* __restrict__ out,
             int out_n) {
    const int e = blockIdx.z;
    const int cnt = g_counts[e];
    const int m0 = blockIdx.y * 128;
    if (m0 >= cnt) return;
    const int off = g_offsets[e];              // padded, multiple of 128
    const int mt = (off >> 7) + blockIdx.y;    // global M-tile index
    const int nt = blockIdx.x;

    __shared__ __align__(16) float fa[2][2048];
    __shared__ __align__(16) float fb[2][2048];

    const int tid = threadIdx.x;
    const int wid = tid >> 5;
    const int lane = tid & 31;
    const int warp_m = wid >> 1;   // 0..3
    const int warp_n = wid & 1;    // 0..1

    const bool isA = (tid < 128);
    const int uid = isA ? tid : tid - 128;
    const float* slab_base = isA
        ? Afrag + (size_t)mt * NCHUNK * 2048
        : Bfrag + ((size_t)e * gridDim.x + nt) * NCHUNK * 2048;
    float* dst0 = isA ? &fa[0][0] : &fb[0][0];

    float c[2][8][4];
#pragma unroll
    for (int mi = 0; mi < 2; mi++)
#pragma unroll
        for (int ni = 0; ni < 8; ni++)
#pragma unroll
            for (int j = 0; j < 4; j++) c[mi][ni][j] = 0.0f;

    float4 rg[4];

#define LOAD_CHUNK(ch) do {                                                    \
    const float* srcp = slab_base + (size_t)(ch) * 2048;                       \
    _Pragma("unroll")                                                          \
    for (int p = 0; p < 4; p++)                                                \
        rg[p] = *(const float4*)(srcp + 4 * (uid + p * 128));                  \
} while (0)

#define STAGE_TO(bufsel) do {                                                  \
    float* dstp = dst0 + (bufsel) * 2048;                                      \
    _Pragma("unroll")                                                          \
    for (int p = 0; p < 4; p++)                                                \
        *(float4*)(dstp + 4 * (uid + p * 128)) = rg[p];                        \
} while (0)

    LOAD_CHUNK(0);
    STAGE_TO(0);
    __syncthreads();

    for (int ch = 0; ch < NCHUNK; ch++) {
        const int b = ch & 1;
        const bool more = (ch + 1 < NCHUNK);
        if (more) LOAD_CHUNK(ch + 1);

#pragma unroll
        for (int s = 0; s < 2; s++) {
            uint4 afr[2];
#pragma unroll
            for (int mi = 0; mi < 2; mi++) {
                int mb = warp_m * 2 + mi;
                afr[mi] = *(const uint4*)&fa[b][(mb * 2 + s) * 128 + lane * 4];
            }
#pragma unroll
            for (int pi = 0; pi < 4; pi++) {
                int pb = warp_n * 4 + pi;
                uint4 bf = *(const uint4*)&fb[b][(pb * 2 + s) * 128 + lane * 4];
#pragma unroll
                for (int mi = 0; mi < 2; mi++) {
                    mma_tf32(c[mi][2 * pi + 0], (const uint32_t*)&afr[mi], bf.x, bf.y);
                    mma_tf32(c[mi][2 * pi + 1], (const uint32_t*)&afr[mi], bf.z, bf.w);
                }
            }
        }
        if (more) STAGE_TO(b ^ 1);
        __syncthreads();
    }
#undef STAGE_TO
#undef LOAD_CHUNK

    const int g = lane >> 2;
    const int t = lane & 3;

    if (FFN1) {
        // Write h in GEMM2 A-fragment layout (out = g_hf).
        const int n0 = nt * 128;
#pragma unroll
        for (int mi = 0; mi < 2; mi++) {
            const int mb = warp_m * 2 + mi;
#pragma unroll
            for (int half = 0; half < 2; half++) {
                int r = warp_m * 32 + mi * 16 + g + half * 8;
                if (m0 + r >= cnt) continue;
#pragma unroll
                for (int ni = 0; ni < 8; ni++) {
                    int ch2 = (n0 + warp_n * 64 + ni * 8) >> 4;
                    int s2 = ni & 1;
                    float* blkp = out + (((size_t)mt * NCH2 + ch2) * 16 + mb * 2 + s2) * 128;
                    int colb = n0 + warp_n * 64 + ni * 8 + t * 2;
                    float2 bb = *(const float2*)(bias + (size_t)e * F_DIM + colb);
#pragma unroll
                    for (int dx = 0; dx < 2; dx++) {
                        float v = c[mi][ni][half * 2 + dx] + (dx ? bb.y : bb.x);
                        v = to_tf32(gelu_exact(v));
                        int tt = t * 2 + dx;
                        int tloc = tt & 3;
                        int colhalf = tt >> 2;
                        int lane2 = g * 4 + tloc;
                        blkp[lane2 * 4 + half + 2 * colhalf] = v;
                    }
                }
            }
        }
    } else {
        const float* brow = bias + (size_t)e * out_n + nt * 128;
#pragma unroll
        for (int mi = 0; mi < 2; mi++) {
#pragma unroll
            for (int half = 0; half < 2; half++) {
                int r = warp_m * 32 + mi * 16 + g + half * 8;
                int mglob = m0 + r;
                if (mglob >= cnt) continue;
                size_t srow = (size_t)(off + mglob);
                float wt = g_sorted_wt[srow];
                float* orow = out + srow * (size_t)out_n + nt * 128;
#pragma unroll
                for (int ni = 0; ni < 8; ni++) {
                    int col = warp_n * 64 + ni * 8 + t * 2;
                    float2 bb = *(const float2*)(brow + col);
                    float2 o;
                    o.x = wt * (c[mi][ni][half * 2 + 0] + bb.x);
                    o.y = wt * (c[mi][ni][half * 2 + 1] + bb.y);
                    *(float2*)(orow + col) = o;
                }
            }
        }
    }
}

// out[t, d] = y[slot0(t), d] + y[slot1(t), d]
__global__ __launch_bounds__(256) void combine_kernel(float* __restrict__ out) {
    int i = blockIdx.x * 256 + threadIdx.x;
    int t = i >> 10;
    int d = i & 1023;
    int s0 = g_slot[2 * t + 0];
    int s1 = g_slot[2 * t + 1];
    out[i] = g_y[(size_t)s0 * D_DIM + d] + g_y[(size_t)s1 * D_DIM + d];
}

// ---------------------------------------------------------------------------
extern "C" void kernel_launch(void* const* d_in, const int* in_sizes, int n_in,
                              void* d_out, int out_size) {
    const float* x  = (const float*)d_in[0];
    const float* gw = (const float*)d_in[1];
    const float* w1 = (const float*)d_in[2];
    const float* b1 = (const float*)d_in[3];
    const float* w2 = (const float*)d_in[4];
    const float* b2 = (const float*)d_in[5];
    float* out = (float*)d_out;

    float* xa;  cudaGetSymbolAddress((void**)&xa,  g_xa);
    float* hf;  cudaGetSymbolAddress((void**)&hf,  g_hf);
    float* w1f; cudaGetSymbolAddress((void**)&w1f, g_w1f);
    float* w2f; cudaGetSymbolAddress((void**)&w2f, g_w2f);
    float* ybuf; cudaGetSymbolAddress((void**)&ybuf, g_y);

    zero_kernel<<<1, 32>>>();
    gate_kernel<<<T_TOK, 256>>>(x, gw);
    scan_kernel<<<1, 32>>>();
    scatter_kernel<<<A_TOT / 256, 256>>>();
    pad_fill_kernel<<<(A_PAD + 255) / 256, 256>>>();

    // Pre-format: weights + gathered activations into fragment slabs.
    wfrag_kernel<<<dim3(NT1, NCH1, E_NUM), 256>>>(w1, w1f, F_DIM);
    wfrag_kernel<<<dim3(NT2, NCH2, E_NUM), 256>>>(w2, w2f, D_DIM);
    xfrag_kernel<<<dim3(NCH1, NMT), 256>>>(x);

    // GEMM1: h = gelu(x @ w1 + b1) -> g_hf (fragment layout)
    ffn_mma<NCH1, 1><<<dim3(NT1, A_TOT / 128, E_NUM), 256>>>(
        xa, w1f, b1, hf, F_DIM);
    // GEMM2: y = wt * (h @ w2 + b2) -> g_y (row-major)
    ffn_mma<NCH2, 0><<<dim3(NT2, A_TOT / 128, E_NUM), 256>>>(
        hf, w2f, b2, ybuf, D_DIM);

    combine_kernel<<<(T_TOK * D_DIM) / 256, 256>>>(out);
}